// round 3
// baseline (speedup 1.0000x reference)
#include <cuda_runtime.h>
#include <cstdint>
#include <cstddef>

#define BB   2
#define NN   1024
#define DN   128
#define DE   16
#define MIDC 64
#define OUTC 128
#define TI   16

// ---------------- scratch (static device arrays; no allocs) ----------------
__device__ __align__(16) float g_p1  [BB*NN*MIDC];   // features @ W1                 (per-j)
__device__ __align__(16) float g_base[BB*NN*MIDC];   // features @ W2 + all biases + g@Wg (per-i)
__device__ __align__(16) float g_vals[BB*NN*OUTC];   // features @ Wm + bm
__device__ __align__(16) float g_skip[BB*NN*OUTC];   // features @ Wskip + bskip
__device__ float g_gw [BB*MIDC];                     // g_features @ Wg
__device__ float g_t  [BB*NN];                       // 0.505 * (p1_row . Wa)
__device__ float g_s2 [BB*NN];                       // ba + 0.505 * (base_row . Wa)
__device__ __align__(16) float g_wea[16];            // 0.505 * (We @ Wa)

// ---------------- helpers ----------------
__device__ __forceinline__ uint32_t f2tf(float x) {
    uint32_t r; asm("cvt.rna.tf32.f32 %0, %1;" : "=r"(r) : "f"(x)); return r;
}
__device__ __forceinline__ unsigned long long pk2(float x, float y) {
    unsigned long long r; asm("mov.b64 %0, {%1, %2};" : "=l"(r) : "f"(x), "f"(y)); return r;
}
__device__ __forceinline__ unsigned long long dup2(float c) {
    unsigned long long r; asm("mov.b64 %0, {%1, %1};" : "=l"(r) : "f"(c)); return r;
}
__device__ __forceinline__ float2 upk(unsigned long long v) {
    float2 f; asm("mov.b64 {%0, %1}, %2;" : "=f"(f.x), "=f"(f.y) : "l"(v)); return f;
}
__device__ __forceinline__ void fma_x2(unsigned long long& d, unsigned long long a, unsigned long long b) {
    asm("fma.rn.f32x2 %0, %1, %2, %0;" : "+l"(d) : "l"(a), "l"(b));
}
__device__ __forceinline__ unsigned long long add_x2(unsigned long long a, unsigned long long b) {
    unsigned long long d; asm("add.rn.f32x2 %0, %1, %2;" : "=l"(d) : "l"(a), "l"(b)); return d;
}
__device__ __forceinline__ unsigned long long abs_x2(unsigned long long x) {
    unsigned long long r; asm("and.b64 %0, %1, 0x7FFFFFFF7FFFFFFF;" : "=l"(r) : "l"(x)); return r;
}
// m16n8k8 tf32 MMA on packed accumulators (c01 = row qid, c23 = row qid+8)
__device__ __forceinline__ void mma_p(unsigned long long& c01, unsigned long long& c23,
                                      const uint32_t a[4], uint32_t b0, uint32_t b1) {
    asm volatile("{\n\t"
        ".reg .f32 f0,f1,f2,f3;\n\t"
        "mov.b64 {f0,f1}, %0;\n\t"
        "mov.b64 {f2,f3}, %1;\n\t"
        "mma.sync.aligned.m16n8k8.row.col.f32.tf32.tf32.f32 "
        "{f0,f1,f2,f3}, {%2,%3,%4,%5}, {%6,%7}, {f0,f1,f2,f3};\n\t"
        "mov.b64 %0, {f0,f1};\n\t"
        "mov.b64 %1, {f2,f3};\n\t"
        "}" : "+l"(c01), "+l"(c23)
            : "r"(a[0]), "r"(a[1]), "r"(a[2]), "r"(a[3]), "r"(b0), "r"(b1));
}

// ---------------- prep 0: g@Wg and We@Wa ----------------
__global__ void prep_g(const float* __restrict__ gf, const float* __restrict__ Wg,
                       const float* __restrict__ We, const float* __restrict__ Wa) {
    int b = blockIdx.x;
    int t = threadIdx.x;
    if (t < MIDC) {
        float acc = 0.f;
        #pragma unroll 8
        for (int c = 0; c < DN; ++c) acc = fmaf(gf[b*DN + c], Wg[c*MIDC + t], acc);
        g_gw[b*MIDC + t] = acc;
    } else if (b == 0 && t < MIDC + DE) {
        int c = t - MIDC;
        float acc = 0.f;
        #pragma unroll
        for (int m = 0; m < MIDC; ++m) acc = fmaf(We[c*MIDC + m], Wa[m], acc);
        g_wea[c] = 0.505f * acc;
    }
}

// ---------------- prep 1: per-node linear terms ----------------
__global__ __launch_bounds__(DN) void prep_rows(
    const float* __restrict__ feat,
    const float* __restrict__ Wm,   const float* __restrict__ bm,
    const float* __restrict__ Wsk,  const float* __restrict__ bsk,
    const float* __restrict__ W1,   const float* __restrict__ b1,
    const float* __restrict__ W2,   const float* __restrict__ b2,
    const float* __restrict__ be,   const float* __restrict__ bg)
{
    __shared__ float f[DN];
    const int row = blockIdx.x;                // b*N + n
    const int b   = row / NN;
    const int t   = threadIdx.x;
    f[t] = feat[(size_t)row*DN + t];
    __syncthreads();

    float a0 = 0.f, a1 = 0.f;
    #pragma unroll 4
    for (int c = 0; c < DN; ++c) {
        float fc = f[c];
        a0 = fmaf(fc, Wm [c*OUTC + t], a0);
        a1 = fmaf(fc, Wsk[c*OUTC + t], a1);
    }
    g_vals[(size_t)row*OUTC + t] = a0 + bm[t];
    g_skip[(size_t)row*OUTC + t] = a1 + bsk[t];

    if (t < MIDC) {
        float a2 = 0.f;
        #pragma unroll 4
        for (int c = 0; c < DN; ++c) a2 = fmaf(f[c], W1[c*MIDC + t], a2);
        g_p1[(size_t)row*MIDC + t] = a2;
    } else {
        const int k = t - MIDC;
        float a3 = 0.f;
        #pragma unroll 4
        for (int c = 0; c < DN; ++c) a3 = fmaf(f[c], W2[c*MIDC + k], a3);
        g_base[(size_t)row*MIDC + k] = a3 + b1[k] + b2[k] + be[k] + bg[k] + g_gw[b*MIDC + k];
    }
}

// ---------------- prep 2: per-row scalar dots with Wa ----------------
__global__ __launch_bounds__(256) void prep_dots(const float* __restrict__ Wa,
                                                 const float* __restrict__ ba) {
    const int w    = threadIdx.x >> 5;
    const int lane = threadIdx.x & 31;
    const int row  = blockIdx.x * 8 + w;       // 0 .. BB*NN-1
    float2 wa2 = ((const float2*)Wa)[lane];
    float2 pa  = ((const float2*)(g_p1   + (size_t)row*MIDC))[lane];
    float2 bb  = ((const float2*)(g_base + (size_t)row*MIDC))[lane];
    float vp = fmaf(pa.y, wa2.y, pa.x*wa2.x);
    float vb = fmaf(bb.y, wa2.y, bb.x*wa2.x);
    #pragma unroll
    for (int o = 16; o >= 1; o >>= 1) {
        vp += __shfl_xor_sync(0xffffffffu, vp, o);
        vb += __shfl_xor_sync(0xffffffffu, vb, o);
    }
    if (lane == 0) {
        g_t [row] = 0.505f * vp;
        g_s2[row] = ba[0] + 0.505f * vb;
    }
}

// ---------------- main fused kernel ----------------
// grid = (NN/TI, BB), block = 256 (8 warps, 2 i-rows per warp)
__global__ __launch_bounds__(256, 1) void gat_main(
    const float* __restrict__ ef,   // (B,N,N,DE)
    const float* __restrict__ adj,  // (B,N,N)
    const float* __restrict__ We,   // (DE,MID)
    const float* __restrict__ Wa,   // (MID,1)
    float* __restrict__ outp)       // (B,N,OUT)
{
    extern __shared__ float sm[];
    float* sLog  = sm;               // TI * NN
    float* sBase = sm + TI*NN;       // TI * MIDC

    const int b    = blockIdx.y;
    const int it0  = blockIdx.x * TI;
    const int tid  = threadIdx.x;
    const int w    = tid >> 5;
    const int lane = tid & 31;
    const int qid  = lane >> 2;      // 0..7
    const int qt   = lane & 3;       // 0..3

    for (int x = tid; x < TI*MIDC; x += 256)
        sBase[x] = g_base[(size_t)(b*NN + it0)*MIDC + x];
    __syncthreads();

    // B fragments under permutations:  k: c = 4q+2s+h ;  n: m = 16*qt' + 2*nt + r
    uint32_t bf[2][8][2];
    {
        const int colb = 16*(qid >> 1) + (qid & 1);
        #pragma unroll
        for (int s = 0; s < 2; ++s)
            #pragma unroll
            for (int nt = 0; nt < 8; ++nt) {
                bf[s][nt][0] = f2tf(We[(4*qt + 2*s    )*MIDC + colb + 2*nt]);
                bf[s][nt][1] = f2tf(We[(4*qt + 2*s + 1)*MIDC + colb + 2*nt]);
            }
    }
    // |x|-half coefficients (0.495*wa), packed pairs for this thread's channels
    unsigned long long waN2[8];
    #pragma unroll
    for (int nt = 0; nt < 8; ++nt)
        waN2[nt] = pk2(0.495f*Wa[16*qt + 2*nt], 0.495f*Wa[16*qt + 2*nt + 1]);
    const float4 wea = ((const float4*)g_wea)[qt];   // 0.505*(We@Wa), this thread's k-slice

    // base pairs + per-i scalar terms, both rows of this warp
    unsigned long long bse[2][8];
    float sI[2];
    #pragma unroll
    for (int il = 0; il < 2; ++il) {
        const int ilocal = 2*w + il;
        const unsigned long long* bp = (const unsigned long long*)(sBase + ilocal*MIDC);
        #pragma unroll
        for (int nt = 0; nt < 8; ++nt) bse[il][nt] = bp[8*qt + nt];
        sI[il] = g_s2[b*NN + it0 + ilocal];
    }

    const float* __restrict__ tbase = g_t + b*NN;
    const float* __restrict__ adjb  = adj + (size_t)b*NN*NN;
    const float4* __restrict__ er0  = (const float4*)ef + ((size_t)(b*NN + it0 + 2*w    ))*NN*(DE/4);
    const float4* __restrict__ er1  = (const float4*)ef + ((size_t)(b*NN + it0 + 2*w + 1))*NN*(DE/4);

    // ---- software pipeline: DRAM operands (ef, adj) prefetched one jt ahead ----
    float4 eA[2], eB[2];
    float  ad[2][2];
    {
        const int j0 = qid;
        eA[0] = __ldg(er0 + (size_t) j0     *(DE/4) + qt);
        eB[0] = __ldg(er0 + (size_t)(j0 + 8)*(DE/4) + qt);
        eA[1] = __ldg(er1 + (size_t) j0     *(DE/4) + qt);
        eB[1] = __ldg(er1 + (size_t)(j0 + 8)*(DE/4) + qt);
        if (qt == 0) {
            ad[0][0] = __ldg(adjb + (size_t)(it0 + 2*w    )*NN + j0);
            ad[0][1] = __ldg(adjb + (size_t)(it0 + 2*w    )*NN + j0 + 8);
            ad[1][0] = __ldg(adjb + (size_t)(it0 + 2*w + 1)*NN + j0);
            ad[1][1] = __ldg(adjb + (size_t)(it0 + 2*w + 1)*NN + j0 + 8);
        }
    }

    // ================= phase 1: logits =================
    #pragma unroll 1
    for (int jt = 0; jt < NN/16; ++jt) {
        const int j0 = jt*16 + qid;

        // p1 pairs (L2-resident), rows j0 and j0+8, this thread's 16 channels
        unsigned long long p1a[8], p1b[8];
        {
            const longlong2* pr  = (const longlong2*)(g_p1 + ((size_t)(b*NN + j0   ))*MIDC);
            const longlong2* pr8 = (const longlong2*)(g_p1 + ((size_t)(b*NN + j0 + 8))*MIDC);
            #pragma unroll
            for (int t = 0; t < 4; ++t) {
                longlong2 la = pr [4*qt + t];
                longlong2 lb = pr8[4*qt + t];
                p1a[2*t] = (unsigned long long)la.x;  p1a[2*t+1] = (unsigned long long)la.y;
                p1b[2*t] = (unsigned long long)lb.x;  p1b[2*t+1] = (unsigned long long)lb.y;
            }
        }
        float tj0 = 0.f, tj1 = 0.f;
        if (qt == 0) { tj0 = tbase[j0]; tj1 = tbase[j0 + 8]; }

        // prefetch next jt's DRAM operands (clamped reload on last iter)
        const int jn = (jt < NN/16 - 1) ? (jt+1)*16 + qid : j0;
        float4 nA[2], nB[2];
        float  nd[2][2];
        nA[0] = __ldg(er0 + (size_t) jn     *(DE/4) + qt);
        nB[0] = __ldg(er0 + (size_t)(jn + 8)*(DE/4) + qt);
        nA[1] = __ldg(er1 + (size_t) jn     *(DE/4) + qt);
        nB[1] = __ldg(er1 + (size_t)(jn + 8)*(DE/4) + qt);
        if (qt == 0) {
            nd[0][0] = __ldg(adjb + (size_t)(it0 + 2*w    )*NN + jn);
            nd[0][1] = __ldg(adjb + (size_t)(it0 + 2*w    )*NN + jn + 8);
            nd[1][0] = __ldg(adjb + (size_t)(it0 + 2*w + 1)*NN + jn);
            nd[1][1] = __ldg(adjb + (size_t)(it0 + 2*w + 1)*NN + jn + 8);
        }

        #pragma unroll
        for (int il = 0; il < 2; ++il) {
            const int ilocal = 2*w + il;
            uint32_t aS0[4] = { f2tf(eA[il].x), f2tf(eB[il].x), f2tf(eA[il].y), f2tf(eB[il].y) };
            uint32_t aS1[4] = { f2tf(eA[il].z), f2tf(eB[il].z), f2tf(eA[il].w), f2tf(eB[il].w) };

            unsigned long long c01[8], c23[8];
            #pragma unroll
            for (int nt = 0; nt < 8; ++nt) {
                c01[nt] = add_x2(bse[il][nt], p1a[nt]);
                c23[nt] = add_x2(bse[il][nt], p1b[nt]);
            }
            #pragma unroll
            for (int nt = 0; nt < 8; ++nt) mma_p(c01[nt], c23[nt], aS0, bf[0][nt][0], bf[0][nt][1]);
            #pragma unroll
            for (int nt = 0; nt < 8; ++nt) mma_p(c01[nt], c23[nt], aS1, bf[1][nt][0], bf[1][nt][1]);

            // |x| half (packed fma pipe; abs on alu pipe)
            unsigned long long P0 = 0ull, P1 = 0ull;
            #pragma unroll
            for (int nt = 0; nt < 8; ++nt) {
                fma_x2(P0, waN2[nt], abs_x2(c01[nt]));
                fma_x2(P1, waN2[nt], abs_x2(c23[nt]));
            }
            // linear half: E . (0.505*We@Wa)
            float lin0 = fmaf(eA[il].w, wea.w, fmaf(eA[il].z, wea.z, fmaf(eA[il].y, wea.y, eA[il].x*wea.x)));
            float lin1 = fmaf(eB[il].w, wea.w, fmaf(eB[il].z, wea.z, fmaf(eB[il].y, wea.y, eB[il].x*wea.x)));
            float2 u0 = upk(P0), u1 = upk(P1);
            float acc0 = u0.x + u0.y + lin0;
            float acc1 = u1.x + u1.y + lin1;
            acc0 += __shfl_xor_sync(0xffffffffu, acc0, 1);
            acc0 += __shfl_xor_sync(0xffffffffu, acc0, 2);
            acc1 += __shfl_xor_sync(0xffffffffu, acc1, 1);
            acc1 += __shfl_xor_sync(0xffffffffu, acc1, 2);
            if (qt == 0) {
                sLog[ilocal*NN + j0    ] = acc0 + sI[il] + tj0 + (ad[il][0] - 1.0f)*1e9f;
                sLog[ilocal*NN + j0 + 8] = acc1 + sI[il] + tj1 + (ad[il][1] - 1.0f)*1e9f;
            }
        }

        eA[0] = nA[0]; eA[1] = nA[1];
        eB[0] = nB[0]; eB[1] = nB[1];
        ad[0][0] = nd[0][0]; ad[0][1] = nd[0][1];
        ad[1][0] = nd[1][0]; ad[1][1] = nd[1][1];
    }
    __syncwarp();

    // ================= phase 2: warp-private softmax (2 rows/warp) =================
    const int r0 = (w << 1), r1 = r0 + 1;
    float inv0, inv1;
    {
        float m0 = -3.0e38f, m1 = -3.0e38f;
        for (int j = lane; j < NN; j += 32) {
            m0 = fmaxf(m0, sLog[r0*NN + j]);
            m1 = fmaxf(m1, sLog[r1*NN + j]);
        }
        #pragma unroll
        for (int o = 16; o >= 1; o >>= 1) {
            m0 = fmaxf(m0, __shfl_xor_sync(0xffffffffu, m0, o));
            m1 = fmaxf(m1, __shfl_xor_sync(0xffffffffu, m1, o));
        }
        float s0 = 0.f, s1 = 0.f;
        for (int j = lane; j < NN; j += 32) {
            float e0v = __expf(sLog[r0*NN + j] - m0);  sLog[r0*NN + j] = e0v;  s0 += e0v;
            float e1v = __expf(sLog[r1*NN + j] - m1);  sLog[r1*NN + j] = e1v;  s1 += e1v;
        }
        #pragma unroll
        for (int o = 16; o >= 1; o >>= 1) {
            s0 += __shfl_xor_sync(0xffffffffu, s0, o);
            s1 += __shfl_xor_sync(0xffffffffu, s1, o);
        }
        inv0 = 1.0f / s0;
        inv1 = 1.0f / s1;
    }
    __syncwarp();

    // ================= phase 3: out = softmax @ values (packed f32x2) =================
    unsigned long long acc00 = 0ull, acc01 = 0ull, acc10 = 0ull, acc11 = 0ull;
    const float4* __restrict__ vrow = (const float4*)(g_vals + (size_t)b*NN*OUTC) + lane;
    const float* __restrict__ l0 = sLog + r0*NN;
    const float* __restrict__ l1 = sLog + r1*NN;
    #pragma unroll 4
    for (int j = 0; j < NN; ++j) {
        float4 v = __ldg(vrow + j*(OUTC/4));
        unsigned long long v01 = pk2(v.x, v.y);
        unsigned long long v23 = pk2(v.z, v.w);
        unsigned long long c0  = dup2(l0[j]);
        unsigned long long c1  = dup2(l1[j]);
        fma_x2(acc00, v01, c0);  fma_x2(acc01, v23, c0);
        fma_x2(acc10, v01, c1);  fma_x2(acc11, v23, c1);
    }
    {
        float2 a0 = upk(acc00), a1 = upk(acc01);
        size_t row = (size_t)(b*NN + it0 + r0);
        float4 sk = __ldg(((const float4*)g_skip) + row*(OUTC/4) + lane);
        float4 o;
        o.x = fmaxf(fmaf(a0.x, inv0, sk.x), 0.f);
        o.y = fmaxf(fmaf(a0.y, inv0, sk.y), 0.f);
        o.z = fmaxf(fmaf(a1.x, inv0, sk.z), 0.f);
        o.w = fmaxf(fmaf(a1.y, inv0, sk.w), 0.f);
        ((float4*)outp)[row*(OUTC/4) + lane] = o;
    }
    {
        float2 a0 = upk(acc10), a1 = upk(acc11);
        size_t row = (size_t)(b*NN + it0 + r1);
        float4 sk = __ldg(((const float4*)g_skip) + row*(OUTC/4) + lane);
        float4 o;
        o.x = fmaxf(fmaf(a0.x, inv1, sk.x), 0.f);
        o.y = fmaxf(fmaf(a0.y, inv1, sk.y), 0.f);
        o.z = fmaxf(fmaf(a1.x, inv1, sk.z), 0.f);
        o.w = fmaxf(fmaf(a1.y, inv1, sk.w), 0.f);
        ((float4*)outp)[row*(OUTC/4) + lane] = o;
    }
}

// ---------------- launch ----------------
extern "C" void kernel_launch(void* const* d_in, const int* in_sizes, int n_in,
                              void* d_out, int out_size)
{
    const float* features   = (const float*)d_in[0];
    const float* e_features = (const float*)d_in[1];
    const float* g_features = (const float*)d_in[2];
    const float* adj        = (const float*)d_in[3];
    const float* Wm         = (const float*)d_in[4];
    const float* bm         = (const float*)d_in[5];
    const float* Wskip      = (const float*)d_in[6];
    const float* bskip      = (const float*)d_in[7];
    const float* W1         = (const float*)d_in[8];
    const float* b1         = (const float*)d_in[9];
    const float* W2         = (const float*)d_in[10];
    const float* b2         = (const float*)d_in[11];
    const float* We         = (const float*)d_in[12];
    const float* be         = (const float*)d_in[13];
    const float* Wg         = (const float*)d_in[14];
    const float* bg         = (const float*)d_in[15];
    const float* Wa         = (const float*)d_in[16];
    const float* ba         = (const float*)d_in[17];
    float* outp = (float*)d_out;

    const int smem_bytes = (TI*NN + TI*MIDC) * (int)sizeof(float);  // 69632
    cudaFuncSetAttribute(gat_main, cudaFuncAttributeMaxDynamicSharedMemorySize, smem_bytes);

    prep_g   <<<BB, MIDC + DE + 16>>>(g_features, Wg, We, Wa);
    prep_rows<<<BB*NN, DN>>>(features, Wm, bm, Wskip, bskip, W1, b1, W2, b2, be, bg);
    prep_dots<<<BB*NN/8, 256>>>(Wa, ba);

    dim3 grid(NN/TI, BB);
    gat_main<<<grid, 256, smem_bytes>>>(e_features, adj, We, Wa, outp);
}